// round 1
// baseline (speedup 1.0000x reference)
#include <cuda_runtime.h>

// LambdaLoss: B=4096 lists, L=128 items each.
// loss = mean over valid lists of [ sum_{i,j: rel_i>rel_j} (rel_i-rel_j)*softplus(-(p_i-p_j)) / cnt ]

#define LL_B 4096
#define LL_L 128

__device__ float g_sum;    // sum of per-list mean losses
__device__ float g_valid;  // number of valid lists

__global__ void ll_init_kernel() {
    g_sum = 0.0f;
    g_valid = 0.0f;
}

__global__ __launch_bounds__(LL_L) void ll_main_kernel(
    const float* __restrict__ pred,
    const float* __restrict__ rel)
{
    __shared__ float sp[LL_L];
    __shared__ float sr[LL_L];
    __shared__ int   hist[8];
    __shared__ float warp_sums[4];

    const int b = blockIdx.x;
    const int j = threadIdx.x;

    const float pj = pred[b * LL_L + j];
    const float rj = rel [b * LL_L + j];
    sp[j] = pj;
    sr[j] = rj;
    if (j < 8) hist[j] = 0;
    __syncthreads();

    // rel values are integers 0..4 stored as float
    atomicAdd(&hist[(int)rj], 1);

    // Pair loop: thread j vs all i. Branch-free:
    //   w  = relu(rel_i - rel_j)            (0 when mask is false or i==j)
    //   sp = softplus(-(p_i - p_j)) = max(-(d),0) + log(1 + exp(-|d|))
    float acc = 0.0f;
#pragma unroll 4
    for (int i = 0; i < LL_L; i++) {
        float rd = sr[i] - rj;
        float w  = fmaxf(rd, 0.0f);
        float d  = sp[i] - pj;
        float t  = __expf(-fabsf(d));          // FMUL + MUFU.EX2
        float lg = __logf(1.0f + t);           // FADD + MUFU.LG2 + FMUL
        float spv = fmaxf(-d, 0.0f) + lg;
        acc = fmaf(w, spv, acc);
    }

    // block reduction of acc (4 warps)
#pragma unroll
    for (int off = 16; off; off >>= 1)
        acc += __shfl_xor_sync(0xffffffffu, acc, off);
    if ((j & 31) == 0) warp_sums[j >> 5] = acc;
    __syncthreads();

    if (j == 0) {
        float s = warp_sums[0] + warp_sums[1] + warp_sums[2] + warp_sums[3];
        int n0 = hist[0], n1 = hist[1], n2 = hist[2], n3 = hist[3], n4 = hist[4];
        // ordered pairs with rel_i > rel_j
        int cnt = n1 * n0
                + n2 * (n0 + n1)
                + n3 * (n0 + n1 + n2)
                + n4 * (n0 + n1 + n2 + n3);
        if (cnt > 0) {
            atomicAdd(&g_sum, s / (float)cnt);
            atomicAdd(&g_valid, 1.0f);
        }
    }
}

__global__ void ll_final_kernel(float* __restrict__ out) {
    out[0] = (g_valid > 0.0f) ? (g_sum / g_valid) : 0.0f;
}

extern "C" void kernel_launch(void* const* d_in, const int* in_sizes, int n_in,
                              void* d_out, int out_size)
{
    const float* pred = (const float*)d_in[0];
    const float* rel  = (const float*)d_in[1];
    float* out = (float*)d_out;

    ll_init_kernel<<<1, 1>>>();
    ll_main_kernel<<<LL_B, LL_L>>>(pred, rel);
    ll_final_kernel<<<1, 1>>>(out);
}

// round 3
// speedup vs baseline: 1.5102x; 1.5102x over previous
#include <cuda_runtime.h>
#include <cstdint>

// LambdaLoss: B=4096 lists, L=128 items.
// loss = mean over valid lists of
//        [ sum_{i,j: rel_i>rel_j} (rel_i-rel_j)*softplus(-(p_i-p_j)) / cnt ]
//
// Key identity: softplus(-d) = max(-d,0) + log(1+exp(-|d|)); the log term is
// symmetric in d, so each UNORDERED pair needs only one exp+log. Sign of the
// rel-difference picks which relu branch applies (weight is 0 at rd==0).

#define LL_B 4096
#define LL_L 128

__device__ float g_sum   = 0.0f;   // sum of per-list mean losses
__device__ int   g_valid = 0;      // number of valid lists
__device__ int   g_done  = 0;      // block arrival counter

__global__ __launch_bounds__(LL_L) void ll_main_kernel(
    const float* __restrict__ pred,
    const float* __restrict__ rel,
    float* __restrict__ out)
{
    __shared__ float sp[LL_L];
    __shared__ float sr[LL_L];
    __shared__ int   hist[8];
    __shared__ float warp_sums[4];

    const int b = blockIdx.x;
    const int j = threadIdx.x;

    const float pj = pred[b * LL_L + j];
    const float rj = rel [b * LL_L + j];
    sp[j] = pj;
    sr[j] = rj;
    if (j < 8) hist[j] = 0;
    __syncthreads();

    // rel values are integers 0..4 stored as float
    atomicAdd(&hist[(int)rj], 1);

    // Unordered-pair ring enumeration: thread j pairs with i=(j+k)&127,
    // k = 1..63 covers every pair at ring-distance 1..63 exactly once;
    // distance-64 pairs are covered once by threads j<64 (extra iteration).
    const unsigned int SIGNBIT = 0x80000000u;
    float acc = 0.0f;

#pragma unroll 7
    for (int k = 1; k < 64; k++) {
        int i = (j + k) & (LL_L - 1);
        float rd = sr[i] - rj;
        float pd = sp[i] - pj;
        // symmetric log term: log(1 + exp(-|pd|))   (one EX2 + one LG2)
        float t  = __expf(-fabsf(pd));
        float lg = __logf(1.0f + t);
        // u = -pd if rd>=0 else +pd  == -(p_winner - p_loser); rd==0 has weight 0
        float u  = __uint_as_float(__float_as_uint(pd)
                                   ^ (__float_as_uint(rd) & SIGNBIT) ^ SIGNBIT);
        acc = fmaf(fabsf(rd), fmaxf(u, 0.0f) + lg, acc);
    }
    // distance-64 pairs: {j, j+64} for j in [0,64)  (warps 0,1 only — uniform)
    if (j < LL_L / 2) {
        int i = j + LL_L / 2;
        float rd = sr[i] - rj;
        float pd = sp[i] - pj;
        float t  = __expf(-fabsf(pd));
        float lg = __logf(1.0f + t);
        float u  = __uint_as_float(__float_as_uint(pd)
                                   ^ (__float_as_uint(rd) & SIGNBIT) ^ SIGNBIT);
        acc = fmaf(fabsf(rd), fmaxf(u, 0.0f) + lg, acc);
    }

    // block reduction (4 warps)
#pragma unroll
    for (int off = 16; off; off >>= 1)
        acc += __shfl_xor_sync(0xffffffffu, acc, off);
    if ((j & 31) == 0) warp_sums[j >> 5] = acc;
    __syncthreads();

    if (j == 0) {
        float s = warp_sums[0] + warp_sums[1] + warp_sums[2] + warp_sums[3];
        int n0 = hist[0], n1 = hist[1], n2 = hist[2], n3 = hist[3], n4 = hist[4];
        int cnt = n1 * n0
                + n2 * (n0 + n1)
                + n3 * (n0 + n1 + n2)
                + n4 * (n0 + n1 + n2 + n3);
        if (cnt > 0) {
            atomicAdd(&g_sum, s / (float)cnt);
            atomicAdd(&g_valid, 1);
        }
        __threadfence();
        int prev = atomicAdd(&g_done, 1);
        if (prev == gridDim.x - 1) {
            // last block: finalize and reset for the next graph replay
            float gs = g_sum;
            int   gv = g_valid;
            out[0] = (gv > 0) ? (gs / (float)gv) : 0.0f;
            g_sum = 0.0f;
            g_valid = 0;
            g_done = 0;
        }
    }
}

extern "C" void kernel_launch(void* const* d_in, const int* in_sizes, int n_in,
                              void* d_out, int out_size)
{
    const float* pred = (const float*)d_in[0];
    const float* rel  = (const float*)d_in[1];
    float* out = (float*)d_out;

    ll_main_kernel<<<LL_B, LL_L>>>(pred, rel, out);
}

// round 4
// speedup vs baseline: 1.9733x; 1.3067x over previous
#include <cuda_runtime.h>
#include <cstdint>

// LambdaLoss: B=4096 lists, L=128 items.
// loss = mean over valid lists of
//        [ sum_{i,j: rel_i>rel_j} (rel_i-rel_j)*softplus(-(p_i-p_j)) / cnt ]
//
// Factorized form: softplus(-(p_w-p_l)) = ln(1 + e^{p_l} * e^{-p_w}).
// Precompute e_i = exp(p_i), rec_i = exp(-p_i) per item (via exp2, log2
// domain; final scale by ln2). Each pair then costs only ONE MUFU (lg2).
//
// 2x2 register tiling: 64 threads per list; thread j owns self items
// {j, j+64}; for k=1..31 it loads items j+k and j+64+k and forms 4 pairs
// (covers all distance-k and distance-(64-k) pairs exactly once); k=32
// contributes 2 pairs (distance 32); {j, j+64} handled in-register.
// 64 threads * 127 pairs = 8128 = C(128,2).

#define LL_B   4096
#define LL_L   128
#define LOG2E  1.4426950408889634f
#define LN2    0.6931471805599453f

__device__ float g_sum   = 0.0f;
__device__ int   g_valid = 0;
__device__ int   g_done  = 0;

__device__ __forceinline__ float fast_ex2(float x) {
    float r;
    asm("ex2.approx.f32 %0, %1;" : "=f"(r) : "f"(x));
    return r;
}
__device__ __forceinline__ float fast_lg2(float x) {
    float r;
    asm("lg2.approx.f32 %0, %1;" : "=f"(r) : "f"(x));
    return r;
}

// One pair (self vs other). v = (e_i, rec_i, rel_i, _).
// rd = rel_i - rel_self; rd>0 -> winner=i: t' = e_self*rec_i
//                        rd<0 -> winner=self: t' = e_i*rec_self
// contribution (log2 units) = |rd| * log2(1 + t')
__device__ __forceinline__ void pair_acc(
    float es, float recs, float rs, const float4& v, float& acc)
{
    float rd    = v.z - rs;
    float m_pos = es * v.y;
    float m_neg = v.x * recs;
    float t     = (rd > 0.0f) ? m_pos : m_neg;
    float lg    = fast_lg2(1.0f + t);
    acc = fmaf(fabsf(rd), lg, acc);
}

__global__ __launch_bounds__(128) void ll_main_kernel(
    const float* __restrict__ pred,
    const float* __restrict__ rel,
    float* __restrict__ out)
{
    // two lists per block; items as (e, rec, rel, pad), duplicated to 160
    __shared__ float4 sitem[2][160];
    __shared__ int    hist[2][8];
    __shared__ float  wsum[4];

    const int t    = threadIdx.x;
    const int half = t >> 6;         // 0 or 1: which list in this block
    const int lj   = t & 63;         // local self index (owns lj and lj+64)
    const int list = blockIdx.x * 2 + half;

    const float* P = pred + list * LL_L;
    const float* R = rel  + list * LL_L;

    const float pA = P[lj];
    const float pB = P[lj + 64];
    const float rA = R[lj];
    const float rB = R[lj + 64];

    const float qA = pA * LOG2E;
    const float qB = pB * LOG2E;
    const float eA = fast_ex2(qA), recA = fast_ex2(-qA);
    const float eB = fast_ex2(qB), recB = fast_ex2(-qB);

    sitem[half][lj]      = make_float4(eA, recA, rA, 0.0f);
    sitem[half][lj + 64] = make_float4(eB, recB, rB, 0.0f);
    if (lj < 32)
        sitem[half][lj + 128] = make_float4(eA, recA, rA, 0.0f);

    if (t < 16) (&hist[0][0])[t] = 0;
    __syncthreads();

    // rel values are integers 0..4
    atomicAdd(&hist[half][(int)rA], 1);
    atomicAdd(&hist[half][(int)rB], 1);

    const float4* S = &sitem[half][0];
    float acc = 0.0f;

#pragma unroll
    for (int k = 1; k < 32; k++) {
        float4 v1 = S[lj + k];        // item j+k
        float4 v2 = S[lj + 64 + k];   // item j+64+k
        pair_acc(eA, recA, rA, v1, acc);   // {j,     j+k}     dist k
        pair_acc(eB, recB, rB, v2, acc);   // {j+64,  j+64+k}  dist k
        pair_acc(eA, recA, rA, v2, acc);   // {j,     j+64+k}  dist 64-k
        pair_acc(eB, recB, rB, v1, acc);   // {j+64,  j+k}     dist 64-k
    }
    {   // k = 32: only the two distance-32 pairs (cross pairs would duplicate)
        float4 v1 = S[lj + 32];
        float4 v2 = S[lj + 96];
        pair_acc(eA, recA, rA, v1, acc);
        pair_acc(eB, recB, rB, v2, acc);
    }
    {   // distance-64 pair {j, j+64}: in-register
        float rd    = rB - rA;
        float m_pos = eA * recB;
        float m_neg = eB * recA;
        float tt    = (rd > 0.0f) ? m_pos : m_neg;
        acc = fmaf(fabsf(rd), fast_lg2(1.0f + tt), acc);
    }

    // reduce within half-block (2 warps per list)
#pragma unroll
    for (int off = 16; off; off >>= 1)
        acc += __shfl_xor_sync(0xffffffffu, acc, off);
    if ((t & 31) == 0) wsum[t >> 5] = acc;
    __syncthreads();

    if (lj == 0) {
        float s = (wsum[half * 2] + wsum[half * 2 + 1]) * LN2;
        int n0 = hist[half][0], n1 = hist[half][1], n2 = hist[half][2];
        int n3 = hist[half][3], n4 = hist[half][4];
        int cnt = n1 * n0
                + n2 * (n0 + n1)
                + n3 * (n0 + n1 + n2)
                + n4 * (n0 + n1 + n2 + n3);
        if (cnt > 0) {
            atomicAdd(&g_sum, s / (float)cnt);
            atomicAdd(&g_valid, 1);
        }
        __threadfence();
        int prev = atomicAdd(&g_done, 1);
        if (prev == LL_B - 1) {
            // last list-leader: finalize and reset for next graph replay
            float gs = g_sum;
            int   gv = g_valid;
            out[0] = (gv > 0) ? (gs / (float)gv) : 0.0f;
            g_sum   = 0.0f;
            g_valid = 0;
            g_done  = 0;
        }
    }
}

extern "C" void kernel_launch(void* const* d_in, const int* in_sizes, int n_in,
                              void* d_out, int out_size)
{
    const float* pred = (const float*)d_in[0];
    const float* rel  = (const float*)d_in[1];
    float* out = (float*)d_out;

    ll_main_kernel<<<LL_B / 2, 128>>>(pred, rel, out);
}

// round 5
// speedup vs baseline: 2.0000x; 1.0135x over previous
#include <cuda_runtime.h>
#include <cstdint>

// LambdaLoss: B=4096 lists, L=128 items.
// loss = mean over valid lists of
//        [ sum_{i,j: rel_i>rel_j} (rel_i-rel_j)*softplus(-(p_i-p_j)) / cnt ]
//
// Factorized: softplus(-(p_w-p_l)) = ln(1 + e^{p_l}*e^{-p_w}); precompute
// e_i = exp(p_i), rec_i = exp(-p_i) per item -> one lg2 per pair.
//
// Counting-sort by rel (ascending) makes pair orientation a function of the
// SORTED INDEX: winner = higher index. 3 of 5 pair kinds become branch-free
// (5 instr/pair); v2 pairs use one index-derived ISETP shared by 2 FSELs.
// Within-class pairs have rd==0 -> contribute exactly 0 in any order.
//
// 2x2 ring tiling over sorted array: 64 threads/list, thread lj owns sorted
// items A=lj, B=lj+64; k=1..31 gives 4 pairs/iter via 2 LDS.128 (dup region
// [128,160) handles ring wrap); k=32 gives 2; plus {A,B}. 127 pairs/thread.

#define LL_B   4096
#define LL_L   128
#define LOG2E  1.4426950408889634f
#define LN2    0.6931471805599453f

__device__ float g_sum   = 0.0f;
__device__ int   g_valid = 0;
__device__ int   g_done  = 0;

__device__ __forceinline__ float fast_ex2(float x) {
    float r; asm("ex2.approx.f32 %0, %1;" : "=f"(r) : "f"(x)); return r;
}
__device__ __forceinline__ float fast_lg2(float x) {
    float r; asm("lg2.approx.f32 %0, %1;" : "=f"(r) : "f"(x)); return r;
}

__global__ __launch_bounds__(128) void ll_main_kernel(
    const float* __restrict__ pred,
    const float* __restrict__ rel,
    float* __restrict__ out)
{
    __shared__ float4 S[2][160];     // sorted (e, rec, rel, _), +32 dup for wrap
    __shared__ int    hist[2][8];
    __shared__ int    base[2][8];
    __shared__ float  wsum[4];

    const int t    = threadIdx.x;
    const int half = t >> 6;
    const int lj   = t & 63;
    const int list = blockIdx.x * 2 + half;

    const float* P = pred + list * LL_L;
    const float* R = rel  + list * LL_L;

    const float p0 = P[lj], p1 = P[lj + 64];
    const float r0 = R[lj], r1 = R[lj + 64];
    const int   c0 = (int)r0, c1 = (int)r1;   // rel in {0..4}

    if (lj < 8) hist[half][lj] = 0;
    __syncthreads();
    atomicAdd(&hist[half][c0], 1);
    atomicAdd(&hist[half][c1], 1);
    __syncthreads();
    if (lj == 0) {
        int a = 0;
#pragma unroll
        for (int c = 0; c < 5; c++) { base[half][c] = a; a += hist[half][c]; }
    }
    __syncthreads();

    // rank + scatter sorted tuples
    const float q0 = p0 * LOG2E, q1 = p1 * LOG2E;
    const int pos0 = atomicAdd(&base[half][c0], 1);
    const int pos1 = atomicAdd(&base[half][c1], 1);
    S[half][pos0] = make_float4(fast_ex2(q0), fast_ex2(-q0), r0, 0.0f);
    S[half][pos1] = make_float4(fast_ex2(q1), fast_ex2(-q1), r1, 0.0f);
    __syncthreads();
    if (lj < 32) S[half][128 + lj] = S[half][lj];   // ring-wrap duplicate
    __syncthreads();

    const float4* Sp = S[half];
    const float4 a = Sp[lj];
    const float4 b = Sp[lj + 64];
    const float eA = a.x, recA = a.y, rA = a.z;
    const float eB = b.x, recB = b.y, rB = b.z;

    float acc0 = 0.0f, acc1 = 0.0f, acc2 = 0.0f, acc3 = 0.0f;

#pragma unroll
    for (int k = 1; k < 32; k++) {
        const float4 v1 = Sp[lj + k];        // sorted idx lj+k   (never wraps)
        const float4 v2 = Sp[lj + 64 + k];   // idx lj+64+k, wraps to lj+k-64
        const bool  nw = (lj + k) < 64;      // no-wrap predicate (index-only)

        // A-v1: v1 higher index -> winner v1 (form1), rd >= 0
        acc0 = fmaf(v1.z - rA, fast_lg2(1.0f + eA * v1.y), acc0);
        // B-v1: B higher index -> winner B (form2), rd >= 0
        acc1 = fmaf(rB - v1.z, fast_lg2(1.0f + v1.x * recB), acc1);
        // A-v2: form1 if no wrap else form2; |rd| covers both
        {
            float rd = fabsf(v2.z - rA);
            float tt = nw ? (eA * v2.y) : (v2.x * recA);
            acc2 = fmaf(rd, fast_lg2(1.0f + tt), acc2);
        }
        // B-v2: same predicate
        {
            float rd = fabsf(v2.z - rB);
            float tt = nw ? (eB * v2.y) : (v2.x * recB);
            acc3 = fmaf(rd, fast_lg2(1.0f + tt), acc3);
        }
    }
    {   // k = 32: two pairs
        const float4 v1 = Sp[lj + 32];       // form1 static
        acc0 = fmaf(v1.z - rA, fast_lg2(1.0f + eA * v1.y), acc0);
        const float4 v2 = Sp[lj + 96];       // wraps for lj >= 32
        const bool nw = lj < 32;
        float rd = fabsf(v2.z - rB);
        float tt = nw ? (eB * v2.y) : (v2.x * recB);
        acc1 = fmaf(rd, fast_lg2(1.0f + tt), acc1);
    }
    // distance-64 pair {A, B}: B higher index (form1 w/ A as loser)
    acc2 = fmaf(rB - rA, fast_lg2(1.0f + eA * recB), acc2);

    float acc = (acc0 + acc1) + (acc2 + acc3);

    // reduce within half-block (2 warps per list)
#pragma unroll
    for (int off = 16; off; off >>= 1)
        acc += __shfl_xor_sync(0xffffffffu, acc, off);
    if ((t & 31) == 0) wsum[t >> 5] = acc;
    __syncthreads();

    if (lj == 0) {
        float s = (wsum[half * 2] + wsum[half * 2 + 1]) * LN2;
        const int n0 = hist[half][0], n1 = hist[half][1], n2 = hist[half][2];
        const int n3 = hist[half][3], n4 = hist[half][4];
        const int cnt = n1 * n0
                      + n2 * (n0 + n1)
                      + n3 * (n0 + n1 + n2)
                      + n4 * (n0 + n1 + n2 + n3);
        if (cnt > 0) {
            atomicAdd(&g_sum, s / (float)cnt);
            atomicAdd(&g_valid, 1);
        }
        __threadfence();
        const int prev = atomicAdd(&g_done, 1);
        if (prev == LL_B - 1) {
            const float gs = g_sum;
            const int   gv = g_valid;
            out[0] = (gv > 0) ? (gs / (float)gv) : 0.0f;
            g_sum   = 0.0f;
            g_valid = 0;
            g_done  = 0;
        }
    }
}

extern "C" void kernel_launch(void* const* d_in, const int* in_sizes, int n_in,
                              void* d_out, int out_size)
{
    const float* pred = (const float*)d_in[0];
    const float* rel  = (const float*)d_in[1];
    float* out = (float*)d_out;

    ll_main_kernel<<<LL_B / 2, 128>>>(pred, rel, out);
}